// round 2
// baseline (speedup 1.0000x reference)
#include <cuda_runtime.h>
#include <cuda_bf16.h>
#include <cstdint>
#include <cstddef>

// ============================ problem dims ============================
static constexpr int E_   = 16;
static constexpr int NTOK = 2048;
static constexpr int DIM  = 1024;
static constexpr int HID  = 4096;

// ============================ scratch (device globals; no allocation) ============================
__device__ __align__(1024) __nv_bfloat16 g_xhi [(size_t)E_ * NTOK * DIM];
__device__ __align__(1024) __nv_bfloat16 g_xlo [(size_t)E_ * NTOK * DIM];
__device__ __align__(1024) __nv_bfloat16 g_w1hi[(size_t)E_ * HID  * DIM];   // [E][H][D] K-major
__device__ __align__(1024) __nv_bfloat16 g_w1lo[(size_t)E_ * HID  * DIM];
__device__ __align__(1024) __nv_bfloat16 g_w2hi[(size_t)E_ * DIM  * HID];   // [E][D][H] K-major
__device__ __align__(1024) __nv_bfloat16 g_w2lo[(size_t)E_ * DIM  * HID];
__device__ __align__(1024) __nv_bfloat16 g_hhi [(size_t)E_ * NTOK * HID];   // hidden split
__device__ __align__(1024) __nv_bfloat16 g_hlo [(size_t)E_ * NTOK * HID];

// ============================ helpers ============================
#define DEVINL __device__ __forceinline__

DEVINL uint32_t smem_u32(const void* p) {
    uint32_t a;
    asm("{ .reg .u64 t; cvta.to.shared.u64 t, %1; cvt.u32.u64 %0, t; }" : "=r"(a) : "l"(p));
    return a;
}

// cp.async 16B
DEVINL void cp_async16(uint32_t smem_addr, const void* gptr) {
    asm volatile("cp.async.cg.shared.global [%0], [%1], 16;" :: "r"(smem_addr), "l"(gptr));
}
DEVINL void cp_commit() { asm volatile("cp.async.commit_group;" ::: "memory"); }
template <int N> DEVINL void cp_wait() { asm volatile("cp.async.wait_group %0;" :: "n"(N) : "memory"); }

DEVINL void ldsm_x4(uint32_t* r, uint32_t addr) {
    asm volatile("ldmatrix.sync.aligned.m8n8.x4.shared.b16 {%0,%1,%2,%3}, [%4];"
                 : "=r"(r[0]), "=r"(r[1]), "=r"(r[2]), "=r"(r[3]) : "r"(addr));
}

DEVINL void mma_bf16(float* c, const uint32_t* a, uint32_t b0, uint32_t b1) {
    asm volatile(
        "mma.sync.aligned.m16n8k16.row.col.f32.bf16.bf16.f32 "
        "{%0,%1,%2,%3}, {%4,%5,%6,%7}, {%8,%9}, {%0,%1,%2,%3};"
        : "+f"(c[0]), "+f"(c[1]), "+f"(c[2]), "+f"(c[3])
        : "r"(a[0]), "r"(a[1]), "r"(a[2]), "r"(a[3]), "r"(b0), "r"(b1));
}

// ============================ numeric helpers ============================
DEVINL void split2(float v, __nv_bfloat16& hi, __nv_bfloat16& lo) {
    hi = __float2bfloat16(v);
    lo = __float2bfloat16(v - __bfloat162float(hi));
}
DEVINL float gelu_exact(float x) {
    return 0.5f * x * (1.0f + erff(x * 0.7071067811865476f));
}
DEVINL uint32_t pack_bf16(__nv_bfloat16 a, __nv_bfloat16 b) {
    return (uint32_t)__bfloat16_as_ushort(a) | ((uint32_t)__bfloat16_as_ushort(b) << 16);
}

// ============================ prep kernels ============================
__global__ void split_x_kernel(const float* __restrict__ in,
                               __nv_bfloat16* __restrict__ hi,
                               __nv_bfloat16* __restrict__ lo, size_t n4) {
    size_t i = (size_t)blockIdx.x * blockDim.x + threadIdx.x;
    size_t stride = (size_t)gridDim.x * blockDim.x;
    for (; i < n4; i += stride) {
        float4 v = reinterpret_cast<const float4*>(in)[i];
        __nv_bfloat16 h0, l0, h1, l1, h2, l2, h3, l3;
        split2(v.x, h0, l0); split2(v.y, h1, l1);
        split2(v.z, h2, l2); split2(v.w, h3, l3);
        reinterpret_cast<uint2*>(hi)[i] = make_uint2(pack_bf16(h0, h1), pack_bf16(h2, h3));
        reinterpret_cast<uint2*>(lo)[i] = make_uint2(pack_bf16(l0, l1), pack_bf16(l2, l3));
    }
}

// transpose [E][R][C] fp32 -> [E][C][R] split bf16 (hi, lo)
__global__ void transpose_split_kernel(const float* __restrict__ in,
                                       __nv_bfloat16* __restrict__ ohi,
                                       __nv_bfloat16* __restrict__ olo,
                                       int R, int C) {
    __shared__ float tile[32][33];
    const int e = blockIdx.z;
    const float* inp = in + (size_t)e * R * C;
    __nv_bfloat16* phi = ohi + (size_t)e * R * C;
    __nv_bfloat16* plo = olo + (size_t)e * R * C;
    const int c0 = blockIdx.x * 32;
    const int r0 = blockIdx.y * 32;
    const int tx = threadIdx.x, ty = threadIdx.y;
#pragma unroll
    for (int j = 0; j < 32; j += 8)
        tile[ty + j][tx] = inp[(size_t)(r0 + ty + j) * C + c0 + tx];
    __syncthreads();
#pragma unroll
    for (int j = 0; j < 32; j += 8) {
        float v = tile[tx][ty + j];
        size_t o = (size_t)(c0 + ty + j) * R + r0 + tx;
        __nv_bfloat16 h, l; split2(v, h, l);
        phi[o] = h;
        plo[o] = l;
    }
}

// ============================ GEMM kernel (mma.sync bf16, 3-term split) ============================
// C[m][n] = Ahi*Bhi + Alo*Bhi + Ahi*Blo  (A row-major K-contig, B [n][k] K-contig)
static constexpr int BM = 128, BN = 128, BK = 32, STAGES = 3;
static constexpr int PITCH = 40;                    // bf16 elems per smem row (80 B, conflict-free)
static constexpr int TILE_B  = BM * PITCH * 2;      // 10240 B
static constexpr int OFF_AH = 0, OFF_AL = TILE_B, OFF_BH = 2 * TILE_B, OFF_BL = 3 * TILE_B;
static constexpr int STAGE_B = 4 * TILE_B;          // 40960 B
static constexpr int SMEM_DYN = STAGES * STAGE_B;   // 122880 B

template <bool GELU_SPLIT, int K, int NB>
__global__ __launch_bounds__(256, 1)
void ffn_gemm(const __nv_bfloat16* __restrict__ Ahi, const __nv_bfloat16* __restrict__ Alo,
              const __nv_bfloat16* __restrict__ Bhi, const __nv_bfloat16* __restrict__ Blo,
              const float* __restrict__ bias,
              float* __restrict__ outF,
              __nv_bfloat16* __restrict__ Ohi, __nv_bfloat16* __restrict__ Olo) {
    extern __shared__ char smem[];
    const uint32_t sbase = smem_u32(smem);
    const int tid  = threadIdx.x;
    const int warp = tid >> 5;
    const int lane = tid & 31;

    const int e  = blockIdx.z;
    const int m0 = blockIdx.y * BM;
    const int n0 = blockIdx.x * BN;

    // global row-base pointers for the loader
    const __nv_bfloat16* gAh = Ahi + ((size_t)e * NTOK + m0) * K;
    const __nv_bfloat16* gAl = Alo + ((size_t)e * NTOK + m0) * K;
    const __nv_bfloat16* gBh = Bhi + ((size_t)e * NB   + n0) * K;
    const __nv_bfloat16* gBl = Blo + ((size_t)e * NB   + n0) * K;

    // loader: 2048 16B-chunks per stage (4 tiles x 128 rows x 4 chunks), 8 per thread
    auto load_stage = [&](int s, int k0) {
        const uint32_t sb = sbase + s * STAGE_B;
#pragma unroll
        for (int j = 0; j < 8; j++) {
            const int c    = j * 256 + tid;
            const int t    = c >> 9;           // 0..3: AH, AL, BH, BL
            const int row  = (c >> 2) & 127;
            const int col  = c & 3;
            const uint32_t saddr = sb + t * TILE_B + row * (PITCH * 2) + col * 16;
            const int goff = row * K + k0 + col * 8;
            const __nv_bfloat16* gp =
                (t == 0) ? gAh + goff : (t == 1) ? gAl + goff :
                (t == 2) ? gBh + goff : gBl + goff;
            cp_async16(saddr, gp);
        }
    };

    // warp tiling: 4(M) x 2(N) warps; warp tile 32(M) x 64(N)
    const int wm = (warp & 3) * 32;
    const int wn = (warp >> 2) * 64;

    // ldmatrix per-thread offsets (relative to tile base, before kk)
    // A (x4, m16k16): rows m.. via lane%16, k half via lane/16
    const int aRow = (lane & 15);
    const int aK   = ((lane >> 4) & 1) * 8;
    // B (x4, two n8 tiles): row n via bits, k half via (lane>>3)&1
    const int bRow = ((lane >> 4) & 1) * 8 + (lane & 7);
    const int bK   = ((lane >> 3) & 1) * 8;

    float acc[2][8][4];
#pragma unroll
    for (int mt = 0; mt < 2; mt++)
#pragma unroll
        for (int nt = 0; nt < 8; nt++)
#pragma unroll
            for (int i = 0; i < 4; i++) acc[mt][nt][i] = 0.0f;

    constexpr int nk = K / BK;

    // prologue: fill STAGES-1 stages
    load_stage(0, 0); cp_commit();
    load_stage(1, BK); cp_commit();

    for (int i = 0; i < nk; i++) {
        cp_wait<STAGES - 2>();
        __syncthreads();
        if (i + STAGES - 1 < nk) {
            load_stage((i + STAGES - 1) % STAGES, (i + STAGES - 1) * BK);
            cp_commit();
        }
        const uint32_t sb = sbase + (i % STAGES) * STAGE_B;

#pragma unroll
        for (int kk = 0; kk < 2; kk++) {
            uint32_t Ah[2][4], Al[2][4], Bh[4][4], Bl[4][4];
#pragma unroll
            for (int mt = 0; mt < 2; mt++) {
                const uint32_t off =
                    (uint32_t)((wm + mt * 16 + aRow) * (PITCH * 2) + (kk * 16 + aK) * 2);
                ldsm_x4(Ah[mt], sb + OFF_AH + off);
                ldsm_x4(Al[mt], sb + OFF_AL + off);
            }
#pragma unroll
            for (int np = 0; np < 4; np++) {
                const uint32_t off =
                    (uint32_t)((wn + np * 16 + bRow) * (PITCH * 2) + (kk * 16 + bK) * 2);
                ldsm_x4(Bh[np], sb + OFF_BH + off);
                ldsm_x4(Bl[np], sb + OFF_BL + off);
            }
            // pass 1: Ahi * Bhi
#pragma unroll
            for (int mt = 0; mt < 2; mt++)
#pragma unroll
                for (int np = 0; np < 4; np++) {
                    mma_bf16(acc[mt][np * 2 + 0], Ah[mt], Bh[np][0], Bh[np][1]);
                    mma_bf16(acc[mt][np * 2 + 1], Ah[mt], Bh[np][2], Bh[np][3]);
                }
            // pass 2: Alo * Bhi
#pragma unroll
            for (int mt = 0; mt < 2; mt++)
#pragma unroll
                for (int np = 0; np < 4; np++) {
                    mma_bf16(acc[mt][np * 2 + 0], Al[mt], Bh[np][0], Bh[np][1]);
                    mma_bf16(acc[mt][np * 2 + 1], Al[mt], Bh[np][2], Bh[np][3]);
                }
            // pass 3: Ahi * Blo
#pragma unroll
            for (int mt = 0; mt < 2; mt++)
#pragma unroll
                for (int np = 0; np < 4; np++) {
                    mma_bf16(acc[mt][np * 2 + 0], Ah[mt], Bl[np][0], Bl[np][1]);
                    mma_bf16(acc[mt][np * 2 + 1], Ah[mt], Bl[np][2], Bl[np][3]);
                }
        }
    }

    // ============================ epilogue ============================
#pragma unroll
    for (int mt = 0; mt < 2; mt++) {
#pragma unroll
        for (int nt = 0; nt < 8; nt++) {
            const int n = n0 + wn + nt * 8 + (lane & 3) * 2;
            const float b0 = bias[n], b1 = bias[n + 1];
#pragma unroll
            for (int half = 0; half < 2; half++) {
                const int m = m0 + wm + mt * 16 + (lane >> 2) + half * 8;
                float v0 = acc[mt][nt][half * 2 + 0] + b0;
                float v1 = acc[mt][nt][half * 2 + 1] + b1;
                const size_t o = ((size_t)e * NTOK + m) * NB + n;
                if constexpr (GELU_SPLIT) {
                    v0 = gelu_exact(v0);
                    v1 = gelu_exact(v1);
                    __nv_bfloat16 h0, l0, h1, l1;
                    split2(v0, h0, l0);
                    split2(v1, h1, l1);
                    *reinterpret_cast<uint32_t*>(Ohi + o) = pack_bf16(h0, h1);
                    *reinterpret_cast<uint32_t*>(Olo + o) = pack_bf16(l0, l1);
                } else {
                    *reinterpret_cast<float2*>(outF + o) = make_float2(v0, v1);
                }
            }
        }
    }
}

// ============================ host launch ============================
extern "C" void kernel_launch(void* const* d_in, const int* in_sizes, int n_in,
                              void* d_out, int out_size) {
    (void)in_sizes; (void)n_in; (void)out_size;
    const float* x  = (const float*)d_in[0];
    const float* w1 = (const float*)d_in[1];
    const float* w2 = (const float*)d_in[2];
    const float* b1 = (const float*)d_in[3];
    const float* b2 = (const float*)d_in[4];
    float* out = (float*)d_out;

    void *xhi, *xlo, *w1hi, *w1lo, *w2hi, *w2lo, *hhi, *hlo;
    cudaGetSymbolAddress(&xhi,  g_xhi);
    cudaGetSymbolAddress(&xlo,  g_xlo);
    cudaGetSymbolAddress(&w1hi, g_w1hi);
    cudaGetSymbolAddress(&w1lo, g_w1lo);
    cudaGetSymbolAddress(&w2hi, g_w2hi);
    cudaGetSymbolAddress(&w2lo, g_w2lo);
    cudaGetSymbolAddress(&hhi,  g_hhi);
    cudaGetSymbolAddress(&hlo,  g_hlo);

    cudaFuncSetAttribute(ffn_gemm<true,  DIM, HID>,
                         cudaFuncAttributeMaxDynamicSharedMemorySize, SMEM_DYN);
    cudaFuncSetAttribute(ffn_gemm<false, HID, DIM>,
                         cudaFuncAttributeMaxDynamicSharedMemorySize, SMEM_DYN);

    // 1) split x into bf16 hi/lo
    const size_t n4 = (size_t)E_ * NTOK * DIM / 4;
    split_x_kernel<<<4096, 256>>>(x, (__nv_bfloat16*)xhi, (__nv_bfloat16*)xlo, n4);

    // 2) transpose + split weights into K-major bf16 hi/lo
    transpose_split_kernel<<<dim3(HID / 32, DIM / 32, E_), dim3(32, 8)>>>(
        w1, (__nv_bfloat16*)w1hi, (__nv_bfloat16*)w1lo, DIM, HID);
    transpose_split_kernel<<<dim3(DIM / 32, HID / 32, E_), dim3(32, 8)>>>(
        w2, (__nv_bfloat16*)w2hi, (__nv_bfloat16*)w2lo, HID, DIM);

    // 3) GEMM1: hidden = gelu(x @ w1 + b1) -> split bf16
    ffn_gemm<true, DIM, HID><<<dim3(HID / BN, NTOK / BM, E_), 256, SMEM_DYN>>>(
        (const __nv_bfloat16*)xhi, (const __nv_bfloat16*)xlo,
        (const __nv_bfloat16*)w1hi, (const __nv_bfloat16*)w1lo,
        b1, nullptr, (__nv_bfloat16*)hhi, (__nv_bfloat16*)hlo);

    // 4) GEMM2: out = hidden @ w2 + b2 -> fp32
    ffn_gemm<false, HID, DIM><<<dim3(DIM / BN, NTOK / BM, E_), 256, SMEM_DYN>>>(
        (const __nv_bfloat16*)hhi, (const __nv_bfloat16*)hlo,
        (const __nv_bfloat16*)w2hi, (const __nv_bfloat16*)w2lo,
        b2, out, nullptr, nullptr);
}

// round 5
// speedup vs baseline: 1.0527x; 1.0527x over previous
#include <cuda_runtime.h>
#include <cuda_bf16.h>
#include <cstdint>
#include <cstddef>

// ============================ problem dims ============================
static constexpr int E_   = 16;
static constexpr int NTOK = 2048;
static constexpr int DIM  = 1024;
static constexpr int HID  = 4096;

// ============================ scratch (device globals; no allocation) ============================
__device__ __align__(1024) __nv_bfloat16 g_xhi [(size_t)E_ * NTOK * DIM];
__device__ __align__(1024) __nv_bfloat16 g_xlo [(size_t)E_ * NTOK * DIM];
__device__ __align__(1024) __nv_bfloat16 g_w1hi[(size_t)E_ * HID  * DIM];   // [E][H][D] K-major
__device__ __align__(1024) __nv_bfloat16 g_w1lo[(size_t)E_ * HID  * DIM];
__device__ __align__(1024) __nv_bfloat16 g_w2hi[(size_t)E_ * DIM  * HID];   // [E][D][H] K-major
__device__ __align__(1024) __nv_bfloat16 g_w2lo[(size_t)E_ * DIM  * HID];
__device__ __align__(1024) __nv_bfloat16 g_hhi [(size_t)E_ * NTOK * HID];   // hidden split
__device__ __align__(1024) __nv_bfloat16 g_hlo [(size_t)E_ * NTOK * HID];

// ============================ helpers ============================
#define DEVINL __device__ __forceinline__

DEVINL uint32_t smem_u32(const void* p) {
    uint32_t a;
    asm("{ .reg .u64 t; cvta.to.shared.u64 t, %1; cvt.u32.u64 %0, t; }" : "=r"(a) : "l"(p));
    return a;
}

// cp.async 16B
DEVINL void cp_async16(uint32_t smem_addr, const void* gptr) {
    asm volatile("cp.async.cg.shared.global [%0], [%1], 16;" :: "r"(smem_addr), "l"(gptr));
}
DEVINL void cp_commit() { asm volatile("cp.async.commit_group;" ::: "memory"); }
template <int N> DEVINL void cp_wait() { asm volatile("cp.async.wait_group %0;" :: "n"(N) : "memory"); }

DEVINL void ldsm_x4(uint32_t* r, uint32_t addr) {
    asm volatile("ldmatrix.sync.aligned.m8n8.x4.shared.b16 {%0,%1,%2,%3}, [%4];"
                 : "=r"(r[0]), "=r"(r[1]), "=r"(r[2]), "=r"(r[3]) : "r"(addr));
}

DEVINL void mma_bf16(float* c, const uint32_t* a, uint32_t b0, uint32_t b1) {
    asm volatile(
        "mma.sync.aligned.m16n8k16.row.col.f32.bf16.bf16.f32 "
        "{%0,%1,%2,%3}, {%4,%5,%6,%7}, {%8,%9}, {%0,%1,%2,%3};"
        : "+f"(c[0]), "+f"(c[1]), "+f"(c[2]), "+f"(c[3])
        : "r"(a[0]), "r"(a[1]), "r"(a[2]), "r"(a[3]), "r"(b0), "r"(b1));
}

// ============================ numeric helpers ============================
DEVINL void split2(float v, __nv_bfloat16& hi, __nv_bfloat16& lo) {
    hi = __float2bfloat16(v);
    lo = __float2bfloat16(v - __bfloat162float(hi));
}
DEVINL float gelu_exact(float x) {
    return 0.5f * x * (1.0f + erff(x * 0.7071067811865476f));
}
DEVINL uint32_t pack_bf16(__nv_bfloat16 a, __nv_bfloat16 b) {
    return (uint32_t)__bfloat16_as_ushort(a) | ((uint32_t)__bfloat16_as_ushort(b) << 16);
}

// ============================ prep kernels ============================
__global__ void split_x_kernel(const float* __restrict__ in,
                               __nv_bfloat16* __restrict__ hi,
                               __nv_bfloat16* __restrict__ lo, size_t n4) {
    size_t i = (size_t)blockIdx.x * blockDim.x + threadIdx.x;
    size_t stride = (size_t)gridDim.x * blockDim.x;
    for (; i < n4; i += stride) {
        float4 v = reinterpret_cast<const float4*>(in)[i];
        __nv_bfloat16 h0, l0, h1, l1, h2, l2, h3, l3;
        split2(v.x, h0, l0); split2(v.y, h1, l1);
        split2(v.z, h2, l2); split2(v.w, h3, l3);
        reinterpret_cast<uint2*>(hi)[i] = make_uint2(pack_bf16(h0, h1), pack_bf16(h2, h3));
        reinterpret_cast<uint2*>(lo)[i] = make_uint2(pack_bf16(l0, l1), pack_bf16(l2, l3));
    }
}

// transpose [E][R][C] fp32 -> [E][C][R] split bf16 (hi, lo)
__global__ void transpose_split_kernel(const float* __restrict__ in,
                                       __nv_bfloat16* __restrict__ ohi,
                                       __nv_bfloat16* __restrict__ olo,
                                       int R, int C) {
    __shared__ float tile[32][33];
    const int e = blockIdx.z;
    const float* inp = in + (size_t)e * R * C;
    __nv_bfloat16* phi = ohi + (size_t)e * R * C;
    __nv_bfloat16* plo = olo + (size_t)e * R * C;
    const int c0 = blockIdx.x * 32;
    const int r0 = blockIdx.y * 32;
    const int tx = threadIdx.x, ty = threadIdx.y;
#pragma unroll
    for (int j = 0; j < 32; j += 8)
        tile[ty + j][tx] = inp[(size_t)(r0 + ty + j) * C + c0 + tx];
    __syncthreads();
#pragma unroll
    for (int j = 0; j < 32; j += 8) {
        float v = tile[tx][ty + j];
        size_t o = (size_t)(c0 + ty + j) * R + r0 + tx;
        __nv_bfloat16 h, l; split2(v, h, l);
        phi[o] = h;
        plo[o] = l;
    }
}

// ============================ GEMM kernel (mma.sync bf16, 3-term split) ============================
// C[m][n] = Ahi*Bhi + Alo*Bhi + Ahi*Blo  (A row-major K-contig, B [n][k] K-contig)
// CTA tile 128x64, warp tile 32x32 (8 warps, 4Mx2N), 3-stage cp.async, 2 CTAs/SM.
static constexpr int BM = 128, BN = 64, BK = 32, STAGES = 3;
static constexpr int PITCH = 40;                    // bf16 elems per smem row (80 B, conflict-free)
static constexpr int ATILE_B = BM * PITCH * 2;      // 10240 B
static constexpr int BTILE_B = BN * PITCH * 2;      // 5120 B
static constexpr int OFF_AH = 0;
static constexpr int OFF_AL = ATILE_B;              // 10240
static constexpr int OFF_BH = 2 * ATILE_B;          // 20480
static constexpr int OFF_BL = 2 * ATILE_B + BTILE_B; // 25600
static constexpr int STAGE_B = 2 * ATILE_B + 2 * BTILE_B;  // 30720 B
static constexpr int SMEM_DYN = STAGES * STAGE_B;   // 92160 B

template <bool GELU_SPLIT, int K, int NB>
__global__ __launch_bounds__(256, 2)
void ffn_gemm(const __nv_bfloat16* __restrict__ Ahi, const __nv_bfloat16* __restrict__ Alo,
              const __nv_bfloat16* __restrict__ Bhi, const __nv_bfloat16* __restrict__ Blo,
              const float* __restrict__ bias,
              float* __restrict__ outF,
              __nv_bfloat16* __restrict__ Ohi, __nv_bfloat16* __restrict__ Olo) {
    extern __shared__ char smem[];
    const uint32_t sbase = smem_u32(smem);
    const int tid  = threadIdx.x;
    const int warp = tid >> 5;
    const int lane = tid & 31;

    const int e  = blockIdx.z;
    const int m0 = blockIdx.y * BM;
    const int n0 = blockIdx.x * BN;

    // global row-base pointers for the loader
    const __nv_bfloat16* gAh = Ahi + ((size_t)e * NTOK + m0) * K;
    const __nv_bfloat16* gAl = Alo + ((size_t)e * NTOK + m0) * K;
    const __nv_bfloat16* gBh = Bhi + ((size_t)e * NB   + n0) * K;
    const __nv_bfloat16* gBl = Blo + ((size_t)e * NB   + n0) * K;

    // loader: 1536 16B-chunks per stage, 6 per thread
    // j=0,1: AH rows 0..127 ; j=2,3: AL ; j=4: BH rows 0..63 ; j=5: BL
    auto load_stage = [&](int s, int k0) {
        const uint32_t sb = sbase + s * STAGE_B;
        const int col  = tid & 3;
        const int goffc = k0 + col * 8;
#pragma unroll
        for (int j = 0; j < 6; j++) {
            int row, off;
            const __nv_bfloat16* base;
            if (j < 2)      { row = (j * 256 + tid) >> 2; off = OFF_AH; base = gAh; }
            else if (j < 4) { row = ((j - 2) * 256 + tid) >> 2; off = OFF_AL; base = gAl; }
            else if (j == 4){ row = tid >> 2; off = OFF_BH; base = gBh; }
            else            { row = tid >> 2; off = OFF_BL; base = gBl; }
            const uint32_t saddr = sb + off + row * (PITCH * 2) + col * 16;
            cp_async16(saddr, base + (size_t)row * K + goffc);
        }
    };

    // warp tiling: 4(M) x 2(N) warps; warp tile 32(M) x 32(N)
    const int wm = (warp & 3) * 32;
    const int wn = (warp >> 2) * 32;

    // ldmatrix per-thread offsets
    const int aRow = (lane & 15);
    const int aK   = ((lane >> 4) & 1) * 8;
    const int bRow = ((lane >> 4) & 1) * 8 + (lane & 7);
    const int bK   = ((lane >> 3) & 1) * 8;

    float acc[2][4][4];
#pragma unroll
    for (int mt = 0; mt < 2; mt++)
#pragma unroll
        for (int nt = 0; nt < 4; nt++)
#pragma unroll
            for (int i = 0; i < 4; i++) acc[mt][nt][i] = 0.0f;

    constexpr int nk = K / BK;

    // prologue: fill STAGES-1 stages
    load_stage(0, 0); cp_commit();
    load_stage(1, BK); cp_commit();

    for (int i = 0; i < nk; i++) {
        cp_wait<STAGES - 2>();
        __syncthreads();
        if (i + STAGES - 1 < nk) {
            load_stage((i + STAGES - 1) % STAGES, (i + STAGES - 1) * BK);
            cp_commit();
        }
        const uint32_t sb = sbase + (i % STAGES) * STAGE_B;

#pragma unroll
        for (int kk = 0; kk < 2; kk++) {
            uint32_t Ah[2][4], Al[2][4], Bh[2][4], Bl[2][4];
#pragma unroll
            for (int mt = 0; mt < 2; mt++) {
                const uint32_t off =
                    (uint32_t)((wm + mt * 16 + aRow) * (PITCH * 2) + (kk * 16 + aK) * 2);
                ldsm_x4(Ah[mt], sb + OFF_AH + off);
                ldsm_x4(Al[mt], sb + OFF_AL + off);
            }
#pragma unroll
            for (int np = 0; np < 2; np++) {
                const uint32_t off =
                    (uint32_t)((wn + np * 16 + bRow) * (PITCH * 2) + (kk * 16 + bK) * 2);
                ldsm_x4(Bh[np], sb + OFF_BH + off);
                ldsm_x4(Bl[np], sb + OFF_BL + off);
            }
            // pass 1: Ahi * Bhi
#pragma unroll
            for (int mt = 0; mt < 2; mt++)
#pragma unroll
                for (int np = 0; np < 2; np++) {
                    mma_bf16(acc[mt][np * 2 + 0], Ah[mt], Bh[np][0], Bh[np][1]);
                    mma_bf16(acc[mt][np * 2 + 1], Ah[mt], Bh[np][2], Bh[np][3]);
                }
            // pass 2: Alo * Bhi
#pragma unroll
            for (int mt = 0; mt < 2; mt++)
#pragma unroll
                for (int np = 0; np < 2; np++) {
                    mma_bf16(acc[mt][np * 2 + 0], Al[mt], Bh[np][0], Bh[np][1]);
                    mma_bf16(acc[mt][np * 2 + 1], Al[mt], Bh[np][2], Bh[np][3]);
                }
            // pass 3: Ahi * Blo
#pragma unroll
            for (int mt = 0; mt < 2; mt++)
#pragma unroll
                for (int np = 0; np < 2; np++) {
                    mma_bf16(acc[mt][np * 2 + 0], Ah[mt], Bl[np][0], Bl[np][1]);
                    mma_bf16(acc[mt][np * 2 + 1], Ah[mt], Bl[np][2], Bl[np][3]);
                }
        }
    }

    // ============================ epilogue ============================
#pragma unroll
    for (int mt = 0; mt < 2; mt++) {
#pragma unroll
        for (int nt = 0; nt < 4; nt++) {
            const int n = n0 + wn + nt * 8 + (lane & 3) * 2;
            const float b0 = bias[n], b1 = bias[n + 1];
#pragma unroll
            for (int half = 0; half < 2; half++) {
                const int m = m0 + wm + mt * 16 + (lane >> 2) + half * 8;
                float v0 = acc[mt][nt][half * 2 + 0] + b0;
                float v1 = acc[mt][nt][half * 2 + 1] + b1;
                const size_t o = ((size_t)e * NTOK + m) * NB + n;
                if constexpr (GELU_SPLIT) {
                    v0 = gelu_exact(v0);
                    v1 = gelu_exact(v1);
                    __nv_bfloat16 h0, l0, h1, l1;
                    split2(v0, h0, l0);
                    split2(v1, h1, l1);
                    *reinterpret_cast<uint32_t*>(Ohi + o) = pack_bf16(h0, h1);
                    *reinterpret_cast<uint32_t*>(Olo + o) = pack_bf16(l0, l1);
                } else {
                    *reinterpret_cast<float2*>(outF + o) = make_float2(v0, v1);
                }
            }
        }
    }
}

// ============================ host launch ============================
extern "C" void kernel_launch(void* const* d_in, const int* in_sizes, int n_in,
                              void* d_out, int out_size) {
    (void)in_sizes; (void)n_in; (void)out_size;
    const float* x  = (const float*)d_in[0];
    const float* w1 = (const float*)d_in[1];
    const float* w2 = (const float*)d_in[2];
    const float* b1 = (const float*)d_in[3];
    const float* b2 = (const float*)d_in[4];
    float* out = (float*)d_out;

    void *xhi, *xlo, *w1hi, *w1lo, *w2hi, *w2lo, *hhi, *hlo;
    cudaGetSymbolAddress(&xhi,  g_xhi);
    cudaGetSymbolAddress(&xlo,  g_xlo);
    cudaGetSymbolAddress(&w1hi, g_w1hi);
    cudaGetSymbolAddress(&w1lo, g_w1lo);
    cudaGetSymbolAddress(&w2hi, g_w2hi);
    cudaGetSymbolAddress(&w2lo, g_w2lo);
    cudaGetSymbolAddress(&hhi,  g_hhi);
    cudaGetSymbolAddress(&hlo,  g_hlo);

    cudaFuncSetAttribute(ffn_gemm<true,  DIM, HID>,
                         cudaFuncAttributeMaxDynamicSharedMemorySize, SMEM_DYN);
    cudaFuncSetAttribute(ffn_gemm<false, HID, DIM>,
                         cudaFuncAttributeMaxDynamicSharedMemorySize, SMEM_DYN);

    // 1) split x into bf16 hi/lo
    const size_t n4 = (size_t)E_ * NTOK * DIM / 4;
    split_x_kernel<<<4096, 256>>>(x, (__nv_bfloat16*)xhi, (__nv_bfloat16*)xlo, n4);

    // 2) transpose + split weights into K-major bf16 hi/lo
    transpose_split_kernel<<<dim3(HID / 32, DIM / 32, E_), dim3(32, 8)>>>(
        w1, (__nv_bfloat16*)w1hi, (__nv_bfloat16*)w1lo, DIM, HID);
    transpose_split_kernel<<<dim3(DIM / 32, HID / 32, E_), dim3(32, 8)>>>(
        w2, (__nv_bfloat16*)w2hi, (__nv_bfloat16*)w2lo, HID, DIM);

    // 3) GEMM1: hidden = gelu(x @ w1 + b1) -> split bf16
    ffn_gemm<true, DIM, HID><<<dim3(HID / BN, NTOK / BM, E_), 256, SMEM_DYN>>>(
        (const __nv_bfloat16*)xhi, (const __nv_bfloat16*)xlo,
        (const __nv_bfloat16*)w1hi, (const __nv_bfloat16*)w1lo,
        b1, nullptr, (__nv_bfloat16*)hhi, (__nv_bfloat16*)hlo);

    // 4) GEMM2: out = hidden @ w2 + b2 -> fp32
    ffn_gemm<false, HID, DIM><<<dim3(DIM / BN, NTOK / BM, E_), 256, SMEM_DYN>>>(
        (const __nv_bfloat16*)hhi, (const __nv_bfloat16*)hlo,
        (const __nv_bfloat16*)w2hi, (const __nv_bfloat16*)w2lo,
        b2, out, nullptr, nullptr);
}

// round 6
// speedup vs baseline: 1.1111x; 1.0555x over previous
#include <cuda_runtime.h>
#include <cuda_bf16.h>
#include <cstdint>
#include <cstddef>

// ============================ problem dims ============================
static constexpr int E_   = 16;
static constexpr int NTOK = 2048;
static constexpr int DIM  = 1024;
static constexpr int HID  = 4096;

// ============================ scratch (device globals; no allocation) ============================
__device__ __align__(1024) __nv_bfloat16 g_xhi [(size_t)E_ * NTOK * DIM];
__device__ __align__(1024) __nv_bfloat16 g_xlo [(size_t)E_ * NTOK * DIM];
__device__ __align__(1024) __nv_bfloat16 g_w1hi[(size_t)E_ * HID  * DIM];   // [E][H][D] K-major
__device__ __align__(1024) __nv_bfloat16 g_w1lo[(size_t)E_ * HID  * DIM];
__device__ __align__(1024) __nv_bfloat16 g_w2hi[(size_t)E_ * DIM  * HID];   // [E][D][H] K-major
__device__ __align__(1024) __nv_bfloat16 g_w2lo[(size_t)E_ * DIM  * HID];
__device__ __align__(1024) __nv_bfloat16 g_hhi [(size_t)E_ * NTOK * HID];   // hidden split
__device__ __align__(1024) __nv_bfloat16 g_hlo [(size_t)E_ * NTOK * HID];

// ============================ helpers ============================
#define DEVINL __device__ __forceinline__

DEVINL uint32_t smem_u32(const void* p) {
    uint32_t a;
    asm("{ .reg .u64 t; cvta.to.shared.u64 t, %1; cvt.u32.u64 %0, t; }" : "=r"(a) : "l"(p));
    return a;
}

// cp.async 16B
DEVINL void cp_async16(uint32_t smem_addr, const void* gptr) {
    asm volatile("cp.async.cg.shared.global [%0], [%1], 16;" :: "r"(smem_addr), "l"(gptr));
}
DEVINL void cp_commit() { asm volatile("cp.async.commit_group;" ::: "memory"); }
template <int N> DEVINL void cp_wait() { asm volatile("cp.async.wait_group %0;" :: "n"(N) : "memory"); }

DEVINL void ldsm_x4(uint32_t* r, uint32_t addr) {
    asm volatile("ldmatrix.sync.aligned.m8n8.x4.shared.b16 {%0,%1,%2,%3}, [%4];"
                 : "=r"(r[0]), "=r"(r[1]), "=r"(r[2]), "=r"(r[3]) : "r"(addr));
}

DEVINL void mma_bf16(float* c, const uint32_t* a, uint32_t b0, uint32_t b1) {
    asm volatile(
        "mma.sync.aligned.m16n8k16.row.col.f32.bf16.bf16.f32 "
        "{%0,%1,%2,%3}, {%4,%5,%6,%7}, {%8,%9}, {%0,%1,%2,%3};"
        : "+f"(c[0]), "+f"(c[1]), "+f"(c[2]), "+f"(c[3])
        : "r"(a[0]), "r"(a[1]), "r"(a[2]), "r"(a[3]), "r"(b0), "r"(b1));
}

// ============================ numeric helpers ============================
DEVINL void split2(float v, __nv_bfloat16& hi, __nv_bfloat16& lo) {
    hi = __float2bfloat16(v);
    lo = __float2bfloat16(v - __bfloat162float(hi));
}
DEVINL float gelu_exact(float x) {
    return 0.5f * x * (1.0f + erff(x * 0.7071067811865476f));
}
DEVINL uint32_t pack_bf16(__nv_bfloat16 a, __nv_bfloat16 b) {
    return (uint32_t)__bfloat16_as_ushort(a) | ((uint32_t)__bfloat16_as_ushort(b) << 16);
}

// ============================ prep kernels ============================
__global__ void split_x_kernel(const float* __restrict__ in,
                               __nv_bfloat16* __restrict__ hi,
                               __nv_bfloat16* __restrict__ lo, size_t n4) {
    size_t i = (size_t)blockIdx.x * blockDim.x + threadIdx.x;
    size_t stride = (size_t)gridDim.x * blockDim.x;
    for (; i < n4; i += stride) {
        float4 v = reinterpret_cast<const float4*>(in)[i];
        __nv_bfloat16 h0, l0, h1, l1, h2, l2, h3, l3;
        split2(v.x, h0, l0); split2(v.y, h1, l1);
        split2(v.z, h2, l2); split2(v.w, h3, l3);
        reinterpret_cast<uint2*>(hi)[i] = make_uint2(pack_bf16(h0, h1), pack_bf16(h2, h3));
        reinterpret_cast<uint2*>(lo)[i] = make_uint2(pack_bf16(l0, l1), pack_bf16(l2, l3));
    }
}

// transpose [E][R][C] fp32 -> [E][C][R] split bf16 (hi, lo)
__global__ void transpose_split_kernel(const float* __restrict__ in,
                                       __nv_bfloat16* __restrict__ ohi,
                                       __nv_bfloat16* __restrict__ olo,
                                       int R, int C) {
    __shared__ float tile[32][33];
    const int e = blockIdx.z;
    const float* inp = in + (size_t)e * R * C;
    __nv_bfloat16* phi = ohi + (size_t)e * R * C;
    __nv_bfloat16* plo = olo + (size_t)e * R * C;
    const int c0 = blockIdx.x * 32;
    const int r0 = blockIdx.y * 32;
    const int tx = threadIdx.x, ty = threadIdx.y;
#pragma unroll
    for (int j = 0; j < 32; j += 8)
        tile[ty + j][tx] = inp[(size_t)(r0 + ty + j) * C + c0 + tx];
    __syncthreads();
#pragma unroll
    for (int j = 0; j < 32; j += 8) {
        float v = tile[tx][ty + j];
        size_t o = (size_t)(c0 + ty + j) * R + r0 + tx;
        __nv_bfloat16 h, l; split2(v, h, l);
        phi[o] = h;
        plo[o] = l;
    }
}

// ============================ GEMM kernel (mma.sync bf16, 3-term split) ============================
// C[m][n] = Ahi*Bhi + Alo*Bhi + Ahi*Blo  (A row-major K-contig, B [n][k] K-contig)
// CTA tile 128x64, warp tile 32x32 (8 warps, 4Mx2N), 3-stage cp.async,
// register-level fragment double buffering, 2 CTAs/SM.
static constexpr int BM = 128, BN = 64, BK = 32, STAGES = 3;
static constexpr int PITCH = 40;                    // bf16 elems per smem row (80 B, conflict-free)
static constexpr int ATILE_B = BM * PITCH * 2;      // 10240 B
static constexpr int BTILE_B = BN * PITCH * 2;      // 5120 B
static constexpr int OFF_AH = 0;
static constexpr int OFF_AL = ATILE_B;              // 10240
static constexpr int OFF_BH = 2 * ATILE_B;          // 20480
static constexpr int OFF_BL = 2 * ATILE_B + BTILE_B; // 25600
static constexpr int STAGE_B = 2 * ATILE_B + 2 * BTILE_B;  // 30720 B
static constexpr int SMEM_DYN = STAGES * STAGE_B;   // 92160 B

template <bool GELU_SPLIT, int K, int NB>
__global__ __launch_bounds__(256, 2)
void ffn_gemm(const __nv_bfloat16* __restrict__ Ahi, const __nv_bfloat16* __restrict__ Alo,
              const __nv_bfloat16* __restrict__ Bhi, const __nv_bfloat16* __restrict__ Blo,
              const float* __restrict__ bias,
              float* __restrict__ outF,
              __nv_bfloat16* __restrict__ Ohi, __nv_bfloat16* __restrict__ Olo) {
    extern __shared__ char smem[];
    const uint32_t sbase = smem_u32(smem);
    const int tid  = threadIdx.x;
    const int warp = tid >> 5;
    const int lane = tid & 31;

    const int e  = blockIdx.z;
    const int m0 = blockIdx.y * BM;
    const int n0 = blockIdx.x * BN;

    // global row-base pointers for the loader
    const __nv_bfloat16* gAh = Ahi + ((size_t)e * NTOK + m0) * K;
    const __nv_bfloat16* gAl = Alo + ((size_t)e * NTOK + m0) * K;
    const __nv_bfloat16* gBh = Bhi + ((size_t)e * NB   + n0) * K;
    const __nv_bfloat16* gBl = Blo + ((size_t)e * NB   + n0) * K;

    // loader: 1536 16B-chunks per stage, 6 per thread
    auto load_stage = [&](int s, int k0) {
        const uint32_t sb = sbase + s * STAGE_B;
        const int col  = tid & 3;
        const int goffc = k0 + col * 8;
#pragma unroll
        for (int j = 0; j < 6; j++) {
            int row, off;
            const __nv_bfloat16* base;
            if (j < 2)      { row = (j * 256 + tid) >> 2; off = OFF_AH; base = gAh; }
            else if (j < 4) { row = ((j - 2) * 256 + tid) >> 2; off = OFF_AL; base = gAl; }
            else if (j == 4){ row = tid >> 2; off = OFF_BH; base = gBh; }
            else            { row = tid >> 2; off = OFF_BL; base = gBl; }
            const uint32_t saddr = sb + off + row * (PITCH * 2) + col * 16;
            cp_async16(saddr, base + (size_t)row * K + goffc);
        }
    };

    // warp tiling: 4(M) x 2(N) warps; warp tile 32(M) x 32(N)
    const int wm = (warp & 3) * 32;
    const int wn = (warp >> 2) * 32;

    // ldmatrix per-thread offsets
    const int aRow = (lane & 15);
    const int aK   = ((lane >> 4) & 1) * 8;
    const int bRow = ((lane >> 4) & 1) * 8 + (lane & 7);
    const int bK   = ((lane >> 3) & 1) * 8;

    // fragment loader for one kk half-step (reads buffer s)
    auto ldsm_all = [&](int s, int kk, uint32_t Ah[2][4], uint32_t Al[2][4],
                        uint32_t Bh[2][4], uint32_t Bl[2][4]) {
        const uint32_t sb = sbase + s * STAGE_B;
#pragma unroll
        for (int mt = 0; mt < 2; mt++) {
            const uint32_t off =
                (uint32_t)((wm + mt * 16 + aRow) * (PITCH * 2) + (kk * 16 + aK) * 2);
            ldsm_x4(Ah[mt], sb + OFF_AH + off);
            ldsm_x4(Al[mt], sb + OFF_AL + off);
        }
#pragma unroll
        for (int np = 0; np < 2; np++) {
            const uint32_t off =
                (uint32_t)((wn + np * 16 + bRow) * (PITCH * 2) + (kk * 16 + bK) * 2);
            ldsm_x4(Bh[np], sb + OFF_BH + off);
            ldsm_x4(Bl[np], sb + OFF_BL + off);
        }
    };

    float acc[2][4][4];
#pragma unroll
    for (int mt = 0; mt < 2; mt++)
#pragma unroll
        for (int nt = 0; nt < 4; nt++)
#pragma unroll
            for (int i = 0; i < 4; i++) acc[mt][nt][i] = 0.0f;

    auto mma_all = [&](uint32_t Ah[2][4], uint32_t Al[2][4],
                       uint32_t Bh[2][4], uint32_t Bl[2][4]) {
        // pass 1: Ahi * Bhi
#pragma unroll
        for (int mt = 0; mt < 2; mt++)
#pragma unroll
            for (int np = 0; np < 2; np++) {
                mma_bf16(acc[mt][np * 2 + 0], Ah[mt], Bh[np][0], Bh[np][1]);
                mma_bf16(acc[mt][np * 2 + 1], Ah[mt], Bh[np][2], Bh[np][3]);
            }
        // pass 2: Alo * Bhi
#pragma unroll
        for (int mt = 0; mt < 2; mt++)
#pragma unroll
            for (int np = 0; np < 2; np++) {
                mma_bf16(acc[mt][np * 2 + 0], Al[mt], Bh[np][0], Bh[np][1]);
                mma_bf16(acc[mt][np * 2 + 1], Al[mt], Bh[np][2], Bh[np][3]);
            }
        // pass 3: Ahi * Blo
#pragma unroll
        for (int mt = 0; mt < 2; mt++)
#pragma unroll
            for (int np = 0; np < 2; np++) {
                mma_bf16(acc[mt][np * 2 + 0], Ah[mt], Bl[np][0], Bl[np][1]);
                mma_bf16(acc[mt][np * 2 + 1], Ah[mt], Bl[np][2], Bl[np][3]);
            }
    };

    constexpr int nk = K / BK;

    // prologue: fill STAGES-1 stages, land stage 0, preload kk=0 fragments
    load_stage(0, 0); cp_commit();
    load_stage(1, BK); cp_commit();
    cp_wait<1>();
    __syncthreads();

    uint32_t Ah0[2][4], Al0[2][4], Bh0[2][4], Bl0[2][4];   // "cur" frags
    uint32_t Ah1[2][4], Al1[2][4], Bh1[2][4], Bl1[2][4];   // "next" frags
    ldsm_all(0, 0, Ah0, Al0, Bh0, Bl0);

    for (int i = 0; i < nk; i++) {
        // half-step kk=0: prefetch kk=1 frags, then MMA on cur frags
        ldsm_all(i % STAGES, 1, Ah1, Al1, Bh1, Bl1);
        mma_all(Ah0, Al0, Bh0, Bl0);

        // stage boundary: advance to stage i+1, prefetch its kk=0 frags;
        // MMAs for kk=1 issue afterwards, hiding barrier + LDSM latency.
        if (i + 1 < nk) {
            __syncthreads();   // all reads of buffer (i+2)%3 (from iter i-1) done
            if (i + 2 < nk) {
                load_stage((i + 2) % STAGES, (i + 2) * BK);
                cp_commit();
                cp_wait<1>();  // pending {i+2} only -> stage i+1 resident
            } else {
                cp_wait<0>();  // last boundary: drain stage i+1
            }
            __syncthreads();   // visibility of stage i+1 across warps
            ldsm_all((i + 1) % STAGES, 0, Ah0, Al0, Bh0, Bl0);
        }
        mma_all(Ah1, Al1, Bh1, Bl1);
    }

    // ============================ epilogue ============================
#pragma unroll
    for (int mt = 0; mt < 2; mt++) {
#pragma unroll
        for (int nt = 0; nt < 4; nt++) {
            const int n = n0 + wn + nt * 8 + (lane & 3) * 2;
            const float b0 = bias[n], b1 = bias[n + 1];
#pragma unroll
            for (int half = 0; half < 2; half++) {
                const int m = m0 + wm + mt * 16 + (lane >> 2) + half * 8;
                float v0 = acc[mt][nt][half * 2 + 0] + b0;
                float v1 = acc[mt][nt][half * 2 + 1] + b1;
                const size_t o = ((size_t)e * NTOK + m) * NB + n;
                if constexpr (GELU_SPLIT) {
                    v0 = gelu_exact(v0);
                    v1 = gelu_exact(v1);
                    __nv_bfloat16 h0, l0, h1, l1;
                    split2(v0, h0, l0);
                    split2(v1, h1, l1);
                    *reinterpret_cast<uint32_t*>(Ohi + o) = pack_bf16(h0, h1);
                    *reinterpret_cast<uint32_t*>(Olo + o) = pack_bf16(l0, l1);
                } else {
                    *reinterpret_cast<float2*>(outF + o) = make_float2(v0, v1);
                }
            }
        }
    }
}

// ============================ host launch ============================
extern "C" void kernel_launch(void* const* d_in, const int* in_sizes, int n_in,
                              void* d_out, int out_size) {
    (void)in_sizes; (void)n_in; (void)out_size;
    const float* x  = (const float*)d_in[0];
    const float* w1 = (const float*)d_in[1];
    const float* w2 = (const float*)d_in[2];
    const float* b1 = (const float*)d_in[3];
    const float* b2 = (const float*)d_in[4];
    float* out = (float*)d_out;

    void *xhi, *xlo, *w1hi, *w1lo, *w2hi, *w2lo, *hhi, *hlo;
    cudaGetSymbolAddress(&xhi,  g_xhi);
    cudaGetSymbolAddress(&xlo,  g_xlo);
    cudaGetSymbolAddress(&w1hi, g_w1hi);
    cudaGetSymbolAddress(&w1lo, g_w1lo);
    cudaGetSymbolAddress(&w2hi, g_w2hi);
    cudaGetSymbolAddress(&w2lo, g_w2lo);
    cudaGetSymbolAddress(&hhi,  g_hhi);
    cudaGetSymbolAddress(&hlo,  g_hlo);

    cudaFuncSetAttribute(ffn_gemm<true,  DIM, HID>,
                         cudaFuncAttributeMaxDynamicSharedMemorySize, SMEM_DYN);
    cudaFuncSetAttribute(ffn_gemm<false, HID, DIM>,
                         cudaFuncAttributeMaxDynamicSharedMemorySize, SMEM_DYN);

    // 1) split x into bf16 hi/lo
    const size_t n4 = (size_t)E_ * NTOK * DIM / 4;
    split_x_kernel<<<4096, 256>>>(x, (__nv_bfloat16*)xhi, (__nv_bfloat16*)xlo, n4);

    // 2) transpose + split weights into K-major bf16 hi/lo
    transpose_split_kernel<<<dim3(HID / 32, DIM / 32, E_), dim3(32, 8)>>>(
        w1, (__nv_bfloat16*)w1hi, (__nv_bfloat16*)w1lo, DIM, HID);
    transpose_split_kernel<<<dim3(DIM / 32, HID / 32, E_), dim3(32, 8)>>>(
        w2, (__nv_bfloat16*)w2hi, (__nv_bfloat16*)w2lo, HID, DIM);

    // 3) GEMM1: hidden = gelu(x @ w1 + b1) -> split bf16
    ffn_gemm<true, DIM, HID><<<dim3(HID / BN, NTOK / BM, E_), 256, SMEM_DYN>>>(
        (const __nv_bfloat16*)xhi, (const __nv_bfloat16*)xlo,
        (const __nv_bfloat16*)w1hi, (const __nv_bfloat16*)w1lo,
        b1, nullptr, (__nv_bfloat16*)hhi, (__nv_bfloat16*)hlo);

    // 4) GEMM2: out = hidden @ w2 + b2 -> fp32
    ffn_gemm<false, HID, DIM><<<dim3(DIM / BN, NTOK / BM, E_), 256, SMEM_DYN>>>(
        (const __nv_bfloat16*)hhi, (const __nv_bfloat16*)hlo,
        (const __nv_bfloat16*)w2hi, (const __nv_bfloat16*)w2lo,
        b2, out, nullptr, nullptr);
}

// round 11
// speedup vs baseline: 2.8895x; 2.6004x over previous
#include <cuda_runtime.h>
#include <cuda_fp16.h>
#include <cstdint>
#include <cstddef>

// ============================ problem dims ============================
static constexpr int E_   = 16;
static constexpr int NTOK = 2048;
static constexpr int DIM  = 1024;
static constexpr int HID  = 4096;

// ============================ scratch (device globals; no allocation) ============================
__device__ __align__(1024) __half g_xh [(size_t)E_ * NTOK * DIM];
__device__ __align__(1024) __half g_w1h[(size_t)E_ * HID  * DIM];   // [E][H][D] K-major
__device__ __align__(1024) __half g_w2h[(size_t)E_ * DIM  * HID];   // [E][D][H] K-major
__device__ __align__(1024) __half g_h  [(size_t)E_ * NTOK * HID];   // hidden fp16

// ============================ helpers ============================
#define DEVINL __device__ __forceinline__

DEVINL uint32_t smem_u32(const void* p) {
    uint32_t a;
    asm("{ .reg .u64 t; cvta.to.shared.u64 t, %1; cvt.u32.u64 %0, t; }" : "=r"(a) : "l"(p));
    return a;
}

// cp.async 16B
DEVINL void cp_async16(uint32_t smem_addr, const void* gptr) {
    asm volatile("cp.async.cg.shared.global [%0], [%1], 16;" :: "r"(smem_addr), "l"(gptr));
}
DEVINL void cp_commit() { asm volatile("cp.async.commit_group;" ::: "memory"); }
template <int N> DEVINL void cp_wait() { asm volatile("cp.async.wait_group %0;" :: "n"(N) : "memory"); }

DEVINL void ldsm_x4(uint32_t* r, uint32_t addr) {
    asm volatile("ldmatrix.sync.aligned.m8n8.x4.shared.b16 {%0,%1,%2,%3}, [%4];"
                 : "=r"(r[0]), "=r"(r[1]), "=r"(r[2]), "=r"(r[3]) : "r"(addr));
}

DEVINL void mma_fp16(float* c, const uint32_t* a, uint32_t b0, uint32_t b1) {
    asm volatile(
        "mma.sync.aligned.m16n8k16.row.col.f32.f16.f16.f32 "
        "{%0,%1,%2,%3}, {%4,%5,%6,%7}, {%8,%9}, {%0,%1,%2,%3};"
        : "+f"(c[0]), "+f"(c[1]), "+f"(c[2]), "+f"(c[3])
        : "r"(a[0]), "r"(a[1]), "r"(a[2]), "r"(a[3]), "r"(b0), "r"(b1));
}

// ============================ numeric helpers ============================
DEVINL float gelu_exact(float x) {
    return 0.5f * x * (1.0f + erff(x * 0.7071067811865476f));
}

// ============================ prep kernels ============================
__global__ void convert_x_kernel(const float* __restrict__ in,
                                 __half* __restrict__ outH, size_t n4) {
    size_t i = (size_t)blockIdx.x * blockDim.x + threadIdx.x;
    size_t stride = (size_t)gridDim.x * blockDim.x;
    for (; i < n4; i += stride) {
        float4 v = reinterpret_cast<const float4*>(in)[i];
        __half2 h0 = __floats2half2_rn(v.x, v.y);
        __half2 h1 = __floats2half2_rn(v.z, v.w);
        reinterpret_cast<uint2*>(outH)[i] =
            make_uint2(*reinterpret_cast<uint32_t*>(&h0), *reinterpret_cast<uint32_t*>(&h1));
    }
}

// transpose [E][R][C] fp32 -> [E][C][R] fp16
__global__ void transpose_half_kernel(const float* __restrict__ in,
                                      __half* __restrict__ outH,
                                      int R, int C) {
    __shared__ float tile[32][33];
    const int e = blockIdx.z;
    const float* inp = in + (size_t)e * R * C;
    __half* ph = outH + (size_t)e * R * C;
    const int c0 = blockIdx.x * 32;
    const int r0 = blockIdx.y * 32;
    const int tx = threadIdx.x, ty = threadIdx.y;
#pragma unroll
    for (int j = 0; j < 32; j += 8)
        tile[ty + j][tx] = inp[(size_t)(r0 + ty + j) * C + c0 + tx];
    __syncthreads();
#pragma unroll
    for (int j = 0; j < 32; j += 8) {
        float v = tile[tx][ty + j];
        size_t o = (size_t)(c0 + ty + j) * R + r0 + tx;
        ph[o] = __float2half(v);
    }
}

// ============================ GEMM kernel (single-pass fp16 mma.sync) ============================
// C[m][n] = A[m][k] * B[n][k]   (A row-major K-contig fp16, B [n][k] K-contig fp16)
// CTA tile 128x128, warp tile 32x64 (8 warps, 4Mx2N), BK=32, 3-stage cp.async, 2 CTAs/SM.
static constexpr int BM = 128, BN = 128, BK = 32, STAGES = 3;
static constexpr int ROW_B  = 80;                   // bytes per smem row (64B data + 16B pad, 16B-aligned)
static constexpr int ATILE_B = BM * ROW_B;          // 10240 B
static constexpr int BTILE_B = BN * ROW_B;          // 10240 B
static constexpr int OFF_A = 0;
static constexpr int OFF_B = ATILE_B;
static constexpr int STAGE_B = ATILE_B + BTILE_B;   // 20480 B
static constexpr int SMEM_DYN = STAGES * STAGE_B;   // 61440 B

template <bool GELU_OUT, int K, int NB>
__global__ __launch_bounds__(256, 2)
void ffn_gemm(const __half* __restrict__ A, const __half* __restrict__ B,
              const float* __restrict__ bias,
              float* __restrict__ outF, __half* __restrict__ outH) {
    extern __shared__ char smem[];
    const uint32_t sbase = smem_u32(smem);
    const int tid  = threadIdx.x;
    const int warp = tid >> 5;
    const int lane = tid & 31;

    const int e  = blockIdx.z;
    const int m0 = blockIdx.y * BM;
    const int n0 = blockIdx.x * BN;

    const __half* gA = A + ((size_t)e * NTOK + m0) * K;
    const __half* gB = B + ((size_t)e * NB   + n0) * K;

    // loader: 1024 16B-chunks per stage (A 512 + B 512), 4 per thread
    auto load_stage = [&](int s, int k0) {
        const uint32_t sb = sbase + s * STAGE_B;
        const int col = tid & 3;
        const int row = tid >> 2;          // 0..63
        const int gk  = k0 + col * 8;
#pragma unroll
        for (int j = 0; j < 2; j++) {
            const int r = j * 64 + row;
            cp_async16(sb + OFF_A + r * ROW_B + col * 16, gA + (size_t)r * K + gk);
        }
#pragma unroll
        for (int j = 0; j < 2; j++) {
            const int r = j * 64 + row;
            cp_async16(sb + OFF_B + r * ROW_B + col * 16, gB + (size_t)r * K + gk);
        }
    };

    // warp tiling: 4(M) x 2(N); warp tile 32(M) x 64(N)
    const int wm = (warp & 3) * 32;
    const int wn = (warp >> 2) * 64;

    // ldmatrix per-thread offsets
    const int aRow = (lane & 15);
    const int aK   = ((lane >> 4) & 1) * 8;
    const int bRow = ((lane >> 4) & 1) * 8 + (lane & 7);
    const int bK   = ((lane >> 3) & 1) * 8;

    float acc[2][8][4];
#pragma unroll
    for (int mt = 0; mt < 2; mt++)
#pragma unroll
        for (int nt = 0; nt < 8; nt++)
#pragma unroll
            for (int i = 0; i < 4; i++) acc[mt][nt][i] = 0.0f;

    constexpr int nk = K / BK;

    // prologue
    load_stage(0, 0); cp_commit();
    load_stage(1, BK); cp_commit();

    for (int i = 0; i < nk; i++) {
        if (i + 1 < nk) cp_wait<1>(); else cp_wait<0>();
        __syncthreads();
        if (i + 2 < nk) {
            load_stage((i + 2) % STAGES, (i + 2) * BK);
            cp_commit();
        }
        const uint32_t sb = sbase + (i % STAGES) * STAGE_B;

#pragma unroll
        for (int kk = 0; kk < 2; kk++) {
            uint32_t Af[2][4], Bf[4][4];
#pragma unroll
            for (int mt = 0; mt < 2; mt++)
                ldsm_x4(Af[mt], sb + OFF_A +
                        (uint32_t)((wm + mt * 16 + aRow) * ROW_B + (kk * 16 + aK) * 2));
#pragma unroll
            for (int np = 0; np < 4; np++)
                ldsm_x4(Bf[np], sb + OFF_B +
                        (uint32_t)((wn + np * 16 + bRow) * ROW_B + (kk * 16 + bK) * 2));
#pragma unroll
            for (int mt = 0; mt < 2; mt++)
#pragma unroll
                for (int np = 0; np < 4; np++) {
                    mma_fp16(acc[mt][np * 2 + 0], Af[mt], Bf[np][0], Bf[np][1]);
                    mma_fp16(acc[mt][np * 2 + 1], Af[mt], Bf[np][2], Bf[np][3]);
                }
        }
    }

    // ============================ epilogue ============================
#pragma unroll
    for (int mt = 0; mt < 2; mt++) {
#pragma unroll
        for (int nt = 0; nt < 8; nt++) {
            const int n = n0 + wn + nt * 8 + (lane & 3) * 2;
            const float b0 = bias[n], b1 = bias[n + 1];
#pragma unroll
            for (int half = 0; half < 2; half++) {
                const int m = m0 + wm + mt * 16 + (lane >> 2) + half * 8;
                float v0 = acc[mt][nt][half * 2 + 0] + b0;
                float v1 = acc[mt][nt][half * 2 + 1] + b1;
                const size_t o = ((size_t)e * NTOK + m) * NB + n;
                if constexpr (GELU_OUT) {
                    v0 = gelu_exact(v0);
                    v1 = gelu_exact(v1);
                    __half2 h = __floats2half2_rn(v0, v1);
                    *reinterpret_cast<uint32_t*>(outH + o) = *reinterpret_cast<uint32_t*>(&h);
                } else {
                    *reinterpret_cast<float2*>(outF + o) = make_float2(v0, v1);
                }
            }
        }
    }
}

// ============================ host launch ============================
extern "C" void kernel_launch(void* const* d_in, const int* in_sizes, int n_in,
                              void* d_out, int out_size) {
    (void)in_sizes; (void)n_in; (void)out_size;
    const float* x  = (const float*)d_in[0];
    const float* w1 = (const float*)d_in[1];
    const float* w2 = (const float*)d_in[2];
    const float* b1 = (const float*)d_in[3];
    const float* b2 = (const float*)d_in[4];
    float* out = (float*)d_out;

    void *xh, *w1h, *w2h, *hh;
    cudaGetSymbolAddress(&xh,  g_xh);
    cudaGetSymbolAddress(&w1h, g_w1h);
    cudaGetSymbolAddress(&w2h, g_w2h);
    cudaGetSymbolAddress(&hh,  g_h);

    cudaFuncSetAttribute(ffn_gemm<true,  DIM, HID>,
                         cudaFuncAttributeMaxDynamicSharedMemorySize, SMEM_DYN);
    cudaFuncSetAttribute(ffn_gemm<false, HID, DIM>,
                         cudaFuncAttributeMaxDynamicSharedMemorySize, SMEM_DYN);

    // 1) convert x -> fp16
    const size_t n4 = (size_t)E_ * NTOK * DIM / 4;
    convert_x_kernel<<<8192, 256>>>(x, (__half*)xh, n4);

    // 2) transpose weights -> K-major fp16
    transpose_half_kernel<<<dim3(HID / 32, DIM / 32, E_), dim3(32, 8)>>>(
        w1, (__half*)w1h, DIM, HID);
    transpose_half_kernel<<<dim3(DIM / 32, HID / 32, E_), dim3(32, 8)>>>(
        w2, (__half*)w2h, HID, DIM);

    // 3) GEMM1: hidden = gelu(x @ w1 + b1) -> fp16
    ffn_gemm<true, DIM, HID><<<dim3(HID / BN, NTOK / BM, E_), 256, SMEM_DYN>>>(
        (const __half*)xh, (const __half*)w1h, b1, nullptr, (__half*)hh);

    // 4) GEMM2: out = hidden @ w2 + b2 -> fp32
    ffn_gemm<false, HID, DIM><<<dim3(DIM / BN, NTOK / BM, E_), 256, SMEM_DYN>>>(
        (const __half*)hh, (const __half*)w2h, b2, out, nullptr);
}

// round 14
// speedup vs baseline: 3.1479x; 1.0894x over previous
#include <cuda_runtime.h>
#include <cuda_fp16.h>
#include <cstdint>
#include <cstddef>

// ============================ problem dims ============================
static constexpr int E_   = 16;
static constexpr int NTOK = 2048;
static constexpr int DIM  = 1024;
static constexpr int HID  = 4096;

// ============================ scratch (device globals; no allocation) ============================
__device__ __align__(1024) __half g_xh [(size_t)E_ * NTOK * DIM];
__device__ __align__(1024) __half g_w1h[(size_t)E_ * HID  * DIM];   // [E][H][D] K-major
__device__ __align__(1024) __half g_w2h[(size_t)E_ * DIM  * HID];   // [E][D][H] K-major
__device__ __align__(1024) __half g_h  [(size_t)E_ * NTOK * HID];   // hidden fp16

// ============================ helpers ============================
#define DEVINL __device__ __forceinline__

DEVINL uint32_t smem_u32(const void* p) {
    uint32_t a;
    asm("{ .reg .u64 t; cvta.to.shared.u64 t, %1; cvt.u32.u64 %0, t; }" : "=r"(a) : "l"(p));
    return a;
}

// cp.async 16B
DEVINL void cp_async16(uint32_t smem_addr, const void* gptr) {
    asm volatile("cp.async.cg.shared.global [%0], [%1], 16;" :: "r"(smem_addr), "l"(gptr));
}
DEVINL void cp_commit() { asm volatile("cp.async.commit_group;" ::: "memory"); }
template <int N> DEVINL void cp_wait() { asm volatile("cp.async.wait_group %0;" :: "n"(N) : "memory"); }

DEVINL void ldsm_x4(uint32_t* r, uint32_t addr) {
    asm volatile("ldmatrix.sync.aligned.m8n8.x4.shared.b16 {%0,%1,%2,%3}, [%4];"
                 : "=r"(r[0]), "=r"(r[1]), "=r"(r[2]), "=r"(r[3]) : "r"(addr));
}

DEVINL void mma_fp16(float* c, const uint32_t* a, uint32_t b0, uint32_t b1) {
    asm volatile(
        "mma.sync.aligned.m16n8k16.row.col.f32.f16.f16.f32 "
        "{%0,%1,%2,%3}, {%4,%5,%6,%7}, {%8,%9}, {%0,%1,%2,%3};"
        : "+f"(c[0]), "+f"(c[1]), "+f"(c[2]), "+f"(c[3])
        : "r"(a[0]), "r"(a[1]), "r"(a[2]), "r"(a[3]), "r"(b0), "r"(b1));
}

// ============================ numeric helpers ============================
DEVINL float gelu_exact(float x) {
    return 0.5f * x * (1.0f + erff(x * 0.7071067811865476f));
}

// ============================ prep kernels ============================
__global__ void convert_x_kernel(const float* __restrict__ in,
                                 __half* __restrict__ outH, size_t n4) {
    size_t i = (size_t)blockIdx.x * blockDim.x + threadIdx.x;
    size_t stride = (size_t)gridDim.x * blockDim.x;
    for (; i < n4; i += stride) {
        float4 v = reinterpret_cast<const float4*>(in)[i];
        __half2 h0 = __floats2half2_rn(v.x, v.y);
        __half2 h1 = __floats2half2_rn(v.z, v.w);
        reinterpret_cast<uint2*>(outH)[i] =
            make_uint2(*reinterpret_cast<uint32_t*>(&h0), *reinterpret_cast<uint32_t*>(&h1));
    }
}

// transpose [E][R][C] fp32 -> [E][C][R] fp16
__global__ void transpose_half_kernel(const float* __restrict__ in,
                                      __half* __restrict__ outH,
                                      int R, int C) {
    __shared__ float tile[32][33];
    const int e = blockIdx.z;
    const float* inp = in + (size_t)e * R * C;
    __half* ph = outH + (size_t)e * R * C;
    const int c0 = blockIdx.x * 32;
    const int r0 = blockIdx.y * 32;
    const int tx = threadIdx.x, ty = threadIdx.y;
#pragma unroll
    for (int j = 0; j < 32; j += 8)
        tile[ty + j][tx] = inp[(size_t)(r0 + ty + j) * C + c0 + tx];
    __syncthreads();
#pragma unroll
    for (int j = 0; j < 32; j += 8) {
        float v = tile[tx][ty + j];
        size_t o = (size_t)(c0 + ty + j) * R + r0 + tx;
        ph[o] = __float2half(v);
    }
}

// ============================ GEMM kernel (single-pass fp16 mma.sync) ============================
// C[m][n] = A[m][k] * B[n][k]   (A row-major K-contig fp16, B [n][k] K-contig fp16)
// CTA tile 128x128, warp tile 32x64 (8 warps, 4Mx2N), BK=64, 2-stage cp.async, 2 CTAs/SM.
static constexpr int BM = 128, BN = 128, BK = 64, STAGES = 2;
static constexpr int ROW_B  = 144;                  // 128B data + 16B pad (16B-aligned, conflict-free)
static constexpr int ATILE_B = BM * ROW_B;          // 18432 B
static constexpr int BTILE_B = BN * ROW_B;          // 18432 B
static constexpr int OFF_A = 0;
static constexpr int OFF_B = ATILE_B;
static constexpr int STAGE_B = ATILE_B + BTILE_B;   // 36864 B
static constexpr int SMEM_DYN = STAGES * STAGE_B;   // 73728 B

template <bool GELU_OUT, int K, int NB>
__global__ __launch_bounds__(256, 2)
void ffn_gemm(const __half* __restrict__ A, const __half* __restrict__ B,
              const float* __restrict__ bias,
              float* __restrict__ outF, __half* __restrict__ outH) {
    extern __shared__ char smem[];
    const uint32_t sbase = smem_u32(smem);
    const int tid  = threadIdx.x;
    const int warp = tid >> 5;
    const int lane = tid & 31;

    const int e  = blockIdx.z;
    const int m0 = blockIdx.y * BM;
    const int n0 = blockIdx.x * BN;

    const __half* gA = A + ((size_t)e * NTOK + m0) * K;
    const __half* gB = B + ((size_t)e * NB   + n0) * K;

    // loader: 2048 16B-chunks per stage (A 1024 + B 1024), 8 per thread
    // per j: row = j-block of 32 rows + tid>>3, col = tid&7
    const int lrow = tid >> 3;          // 0..31
    const int lcol = tid & 7;           // 0..7
    auto load_stage = [&](int s, int k0) {
        const uint32_t sb = sbase + s * STAGE_B;
        const int gk = k0 + lcol * 8;
#pragma unroll
        for (int j = 0; j < 4; j++) {
            const int r = j * 32 + lrow;
            cp_async16(sb + OFF_A + r * ROW_B + lcol * 16, gA + (size_t)r * K + gk);
        }
#pragma unroll
        for (int j = 0; j < 4; j++) {
            const int r = j * 32 + lrow;
            cp_async16(sb + OFF_B + r * ROW_B + lcol * 16, gB + (size_t)r * K + gk);
        }
    };

    // warp tiling: 4(M) x 2(N); warp tile 32(M) x 64(N)
    const int wm = (warp & 3) * 32;
    const int wn = (warp >> 2) * 64;

    // hoisted ldmatrix per-thread base offsets (add sb + kk*32 in the loop)
    const int aRow = (lane & 15);
    const int aK   = ((lane >> 4) & 1) * 8;
    const int bRow = ((lane >> 4) & 1) * 8 + (lane & 7);
    const int bK   = ((lane >> 3) & 1) * 8;
    uint32_t aBase[2], bBase[4];
#pragma unroll
    for (int mt = 0; mt < 2; mt++)
        aBase[mt] = OFF_A + (uint32_t)((wm + mt * 16 + aRow) * ROW_B + aK * 2);
#pragma unroll
    for (int np = 0; np < 4; np++)
        bBase[np] = OFF_B + (uint32_t)((wn + np * 16 + bRow) * ROW_B + bK * 2);

    float acc[2][8][4];
#pragma unroll
    for (int mt = 0; mt < 2; mt++)
#pragma unroll
        for (int nt = 0; nt < 8; nt++)
#pragma unroll
            for (int i = 0; i < 4; i++) acc[mt][nt][i] = 0.0f;

    constexpr int nk = K / BK;

    // prologue: load stage 0
    load_stage(0, 0); cp_commit();

    for (int i = 0; i < nk; i++) {
        cp_wait<0>();          // stage i resident (single outstanding group)
        __syncthreads();
        if (i + 1 < nk) {      // prefetch next stage into the other buffer
            load_stage((i + 1) & 1, (i + 1) * BK);
            cp_commit();
        }
        const uint32_t sb = sbase + (i & 1) * STAGE_B;

#pragma unroll
        for (int kk = 0; kk < 4; kk++) {
            const uint32_t ko = (uint32_t)(kk * 32);   // 16 elems * 2B per kk step
            uint32_t Af[2][4], Bf[4][4];
#pragma unroll
            for (int mt = 0; mt < 2; mt++)
                ldsm_x4(Af[mt], sb + aBase[mt] + ko);
#pragma unroll
            for (int np = 0; np < 4; np++)
                ldsm_x4(Bf[np], sb + bBase[np] + ko);
#pragma unroll
            for (int mt = 0; mt < 2; mt++)
#pragma unroll
                for (int np = 0; np < 4; np++) {
                    mma_fp16(acc[mt][np * 2 + 0], Af[mt], Bf[np][0], Bf[np][1]);
                    mma_fp16(acc[mt][np * 2 + 1], Af[mt], Bf[np][2], Bf[np][3]);
                }
        }
        __syncthreads();       // all warps done reading stage i before it is overwritten
    }

    // ============================ epilogue ============================
#pragma unroll
    for (int mt = 0; mt < 2; mt++) {
#pragma unroll
        for (int nt = 0; nt < 8; nt++) {
            const int n = n0 + wn + nt * 8 + (lane & 3) * 2;
            const float b0 = bias[n], b1 = bias[n + 1];
#pragma unroll
            for (int half = 0; half < 2; half++) {
                const int m = m0 + wm + mt * 16 + (lane >> 2) + half * 8;
                float v0 = acc[mt][nt][half * 2 + 0] + b0;
                float v1 = acc[mt][nt][half * 2 + 1] + b1;
                const size_t o = ((size_t)e * NTOK + m) * NB + n;
                if constexpr (GELU_OUT) {
                    v0 = gelu_exact(v0);
                    v1 = gelu_exact(v1);
                    __half2 h = __floats2half2_rn(v0, v1);
                    *reinterpret_cast<uint32_t*>(outH + o) = *reinterpret_cast<uint32_t*>(&h);
                } else {
                    *reinterpret_cast<float2*>(outF + o) = make_float2(v0, v1);
                }
            }
        }
    }
}

// ============================ host launch ============================
extern "C" void kernel_launch(void* const* d_in, const int* in_sizes, int n_in,
                              void* d_out, int out_size) {
    (void)in_sizes; (void)n_in; (void)out_size;
    const float* x  = (const float*)d_in[0];
    const float* w1 = (const float*)d_in[1];
    const float* w2 = (const float*)d_in[2];
    const float* b1 = (const float*)d_in[3];
    const float* b2 = (const float*)d_in[4];
    float* out = (float*)d_out;

    void *xh, *w1h, *w2h, *hh;
    cudaGetSymbolAddress(&xh,  g_xh);
    cudaGetSymbolAddress(&w1h, g_w1h);
    cudaGetSymbolAddress(&w2h, g_w2h);
    cudaGetSymbolAddress(&hh,  g_h);

    cudaFuncSetAttribute(ffn_gemm<true,  DIM, HID>,
                         cudaFuncAttributeMaxDynamicSharedMemorySize, SMEM_DYN);
    cudaFuncSetAttribute(ffn_gemm<false, HID, DIM>,
                         cudaFuncAttributeMaxDynamicSharedMemorySize, SMEM_DYN);

    // 1) convert x -> fp16
    const size_t n4 = (size_t)E_ * NTOK * DIM / 4;
    convert_x_kernel<<<8192, 256>>>(x, (__half*)xh, n4);

    // 2) transpose weights -> K-major fp16
    transpose_half_kernel<<<dim3(HID / 32, DIM / 32, E_), dim3(32, 8)>>>(
        w1, (__half*)w1h, DIM, HID);
    transpose_half_kernel<<<dim3(DIM / 32, HID / 32, E_), dim3(32, 8)>>>(
        w2, (__half*)w2h, HID, DIM);

    // 3) GEMM1: hidden = gelu(x @ w1 + b1) -> fp16
    ffn_gemm<true, DIM, HID><<<dim3(HID / BN, NTOK / BM, E_), 256, SMEM_DYN>>>(
        (const __half*)xh, (const __half*)w1h, b1, nullptr, (__half*)hh);

    // 4) GEMM2: out = hidden @ w2 + b2 -> fp32
    ffn_gemm<false, HID, DIM><<<dim3(DIM / BN, NTOK / BM, E_), 256, SMEM_DYN>>>(
        (const __half*)hh, (const __half*)w2h, b2, out, nullptr);
}